// round 15
// baseline (speedup 1.0000x reference)
#include <cuda_runtime.h>
#include <cuda_bf16.h>
#include <cuda_fp16.h>
#include <math.h>
#include <stdint.h>

#define BSZ  8192
#define INPD 3072
#define HIDD 1024
#define OUTD 768
#define LN_EPS 1e-5f
#define NTILE_S 64            // 8192 / 128 column tiles in the S GEMM

// ===========================================================================
// Scratch (__device__ globals; no allocations allowed anywhere).
// ===========================================================================
__device__ float g_P[(size_t)BSZ * OUTD];
__device__ double g_loss;
__device__ int    g_correct;

// per-(row, col-tile) online-softmax partials for S
__device__ float g_pM[(size_t)BSZ * NTILE_S];
__device__ float g_pS[(size_t)BSZ * NTILE_S];
__device__ int   g_pI[(size_t)BSZ * NTILE_S];

// fp16 operand buffers (activations)
__device__ __half g_A1h[(size_t)BSZ * INPD];
__device__ float  g_H[(size_t)BSZ * HIDD];       // f32 residual stream
__device__ __half g_Hh[(size_t)BSZ * HIDD];
__device__ __half g_Hl[(size_t)BSZ * HIDD];
__device__ __half g_Th[(size_t)BSZ * HIDD];
// fp16 operands for the S GEMM
__device__ __half g_PN16[(size_t)BSZ * OUTD];
__device__ __half g_YN16[(size_t)BSZ * OUTD];
// transposed weights: [N rows][K cols], K-major, fp16
__device__ __half g_W1h[(size_t)HIDD * INPD];
__device__ __half g_Wah[(size_t)HIDD * HIDD];
__device__ __half g_Wbh[(size_t)HIDD * HIDD];
__device__ __half g_W2h[(size_t)OUTD * HIDD];

// ===========================================================================
// Helpers (base compute_103 features only: mma.sync / ldmatrix / cp.async)
// ===========================================================================
__device__ __forceinline__ uint32_t smem_to_u32(const void* p) {
    uint32_t a;
    asm("{ .reg .u64 t; cvta.to.shared.u64 t, %1; cvt.u32.u64 %0, t; }"
        : "=r"(a) : "l"(p));
    return a;
}

__device__ __forceinline__ void cp_async16(uint32_t saddr, const void* gaddr) {
    asm volatile("cp.async.cg.shared.global [%0], [%1], 16;"
                 :: "r"(saddr), "l"(gaddr) : "memory");
}
__device__ __forceinline__ void cp_commit() {
    asm volatile("cp.async.commit_group;" ::: "memory");
}
template <int N>
__device__ __forceinline__ void cp_wait() {
    asm volatile("cp.async.wait_group %0;" :: "n"(N) : "memory");
}

__device__ __forceinline__ void ldsm4(uint32_t* r, uint32_t addr) {
    asm volatile("ldmatrix.sync.aligned.m8n8.x4.shared.b16 {%0,%1,%2,%3}, [%4];"
                 : "=r"(r[0]), "=r"(r[1]), "=r"(r[2]), "=r"(r[3]) : "r"(addr));
}

__device__ __forceinline__ void mma_f16(float* c, const uint32_t* a,
                                        uint32_t b0, uint32_t b1) {
    asm volatile(
        "mma.sync.aligned.m16n8k16.row.col.f32.f16.f16.f32 "
        "{%0,%1,%2,%3}, {%4,%5,%6,%7}, {%8,%9}, {%0,%1,%2,%3};"
        : "+f"(c[0]), "+f"(c[1]), "+f"(c[2]), "+f"(c[3])
        : "r"(a[0]), "r"(a[1]), "r"(a[2]), "r"(a[3]), "r"(b0), "r"(b1));
}

__device__ __forceinline__ void split_f16(float v, __half& h, __half& l) {
    h = __float2half_rn(v);
    l = __float2half_rn(v - __half2float(h));
}

// online-softmax pairwise merge (m, s, first-max index)
__device__ __forceinline__ void olmerge(float& m1, float& s1, int& i1,
                                        float m2, float s2, int i2) {
    if (m2 > m1)      { s1 = s2 + s1 * __expf(m1 - m2); m1 = m2; i1 = i2; }
    else if (m2 < m1) { s1 = s1 + s2 * __expf(m2 - m1); }
    else              { s1 = s1 + s2; i1 = min(i1, i2); }
}

// ===========================================================================
// tsplit_all: transpose + fp16-quantize all four weights in ONE launch.
// ===========================================================================
__global__ void tsplit_all_kernel(const float* __restrict__ W1,
                                  const float* __restrict__ Wa,
                                  const float* __restrict__ Wb,
                                  const float* __restrict__ W2)
{
    const float* W; __half* TH; int K, N;
    switch (blockIdx.z) {
        case 0: W = W1; TH = g_W1h; K = INPD; N = HIDD; break;
        case 1: W = Wa; TH = g_Wah; K = HIDD; N = HIDD; break;
        case 2: W = Wb; TH = g_Wbh; K = HIDD; N = HIDD; break;
        default: W = W2; TH = g_W2h; K = HIDD; N = OUTD; break;
    }
    int k0 = blockIdx.x * 32, n0 = blockIdx.y * 32;
    if (k0 >= K || n0 >= N) return;

    __shared__ float t[32][33];
    int tx = threadIdx.x, ty = threadIdx.y;   // 32 x 8
#pragma unroll
    for (int i = 0; i < 32; i += 8)
        t[ty + i][tx] = W[(size_t)(k0 + ty + i) * N + n0 + tx];
    __syncthreads();
#pragma unroll
    for (int i = 0; i < 32; i += 8) {
        float v = t[tx][ty + i];
        size_t o = (size_t)(n0 + ty + i) * K + k0 + tx;
        TH[o] = __float2half_rn(v);
    }
}

// LN1 -> fp16 (also zeroes the loss accumulators from block 0).
__global__ void ln1_split_kernel(const float* __restrict__ x,
                                 const float* __restrict__ g,
                                 const float* __restrict__ b)
{
    int row = blockIdx.x, tid = threadIdx.x;
    if (row == 0 && tid == 0) { g_loss = 0.0; g_correct = 0; }
    const float* xr = x + (size_t)row * INPD;
    float v[12];
    float s = 0.f, ss = 0.f;
#pragma unroll
    for (int i = 0; i < 12; i++) {
        int j = tid + i * 256;
        v[i] = xr[j];
        s += v[i]; ss += v[i] * v[i];
    }
    __shared__ float sh[256], sh2[256];
    sh[tid] = s; sh2[tid] = ss;
    __syncthreads();
    for (int o = 128; o > 0; o >>= 1) {
        if (tid < o) { sh[tid] += sh[tid + o]; sh2[tid] += sh2[tid + o]; }
        __syncthreads();
    }
    __shared__ float sm, sr;
    if (tid == 0) {
        float m = sh[0] / (float)INPD;
        float var = sh2[0] / (float)INPD - m * m;
        sm = m; sr = rsqrtf(var + LN_EPS);
    }
    __syncthreads();
    float m = sm, r = sr;
#pragma unroll
    for (int i = 0; i < 12; i++) {
        int j = tid + i * 256;
        float t = (v[i] - m) * r * g[j] + b[j];
        g_A1h[(size_t)row * INPD + j] = __float2half_rn(t);
    }
}

// ===========================================================================
// Persistent tensor-core GEMM via fp16 mma.sync: C[M,N] = ep(A @ B^T)
// NSPLIT=2: A pair x B single, 2 MMAs, 2-stage ring.
// NSPLIT=1: A single x B single, 1 MMA, 4-stage ring (3 chunks in flight).
// DO_S: emit per-(row, col-tile) online-softmax partials instead of storing C.
// Block tile 256x128, 8 warps (4m x 2n), warp tile 64x64, k-chunk 64.
// ===========================================================================
#define SMS    144                      // smem row stride in bytes (128 + 16 pad)
#define A_BUF  (256 * SMS)              // 36864
#define B_BUF  (128 * SMS)              // 18432
#define GEMM_SMEM_BYTES 221184          // max(4 * 55296, 2 * 92160)

template <int NSPLIT, bool DO_S>
__global__ void __launch_bounds__(256, 1)
tc_gemm(const __half* __restrict__ AHi, const __half* __restrict__ ALo,
        const __half* __restrict__ BHi,
        const float* __restrict__ bias, const float* __restrict__ resid,
        float* __restrict__ C,
        __half* __restrict__ CHi, __half* __restrict__ CLo,
        int M, int N, int K, int doRelu)
{
    constexpr int NST    = (NSPLIT >= 2) ? 2 : 4;
    constexpr int OFF_AL = A_BUF;                                  // NSPLIT=2 only
    constexpr int OFF_B  = (NSPLIT >= 2) ? 2 * A_BUF : A_BUF;
    constexpr int ST_SZ  = (NSPLIT >= 2) ? (2 * A_BUF + B_BUF) : (A_BUF + B_BUF);

    extern __shared__ char smem[];
    const uint32_t sbase = smem_to_u32(smem);
    const int tid = threadIdx.x;
    const int wid = tid >> 5, lid = tid & 31;
    const int wm = wid & 3, wn = wid >> 2;     // 4m x 2n warp grid
    const size_t ldb = (size_t)K * 2;          // bytes per row
    const int nch = K >> 6;                    // k-chunks of 64
    const int ntN = N >> 7, ntM = M >> 8;
    const int ntotal = ntN * ntM;

    const uint32_t aOff = (uint32_t)((wm * 64 + (lid & 15)) * SMS) + ((lid >> 4) << 4);
    const uint32_t bOff = (uint32_t)((wn * 64 + (lid & 7) + ((lid >> 4) << 3)) * SMS)
                        + (((lid >> 3) & 1) << 4);

    for (int t = blockIdx.x; t < ntotal; t += gridDim.x) {
        const int bx = t % ntN, by = t / ntN;
        const int m0 = by * 256, n0 = bx * 128;
        const char* gAh = (const char*)AHi + (size_t)m0 * ldb;
        const char* gAl = (const char*)ALo + (size_t)m0 * ldb;
        const char* gBh = (const char*)BHi + (size_t)n0 * ldb;

        float acc[4][8][4];
#pragma unroll
        for (int i = 0; i < 4; i++)
#pragma unroll
            for (int j = 0; j < 8; j++)
#pragma unroll
                for (int q = 0; q < 4; q++) acc[i][j][q] = 0.f;

        auto issue = [&](int kt) {
            const uint32_t st = sbase + (uint32_t)(kt % NST) * ST_SZ;
            const size_t kb = (size_t)kt << 7;     // 64 elems = 128 bytes
#pragma unroll
            for (int it = 0; it < 8; it++) {
                int idx = it * 256 + tid;
                int row = idx >> 3;
                uint32_t chb = (uint32_t)(idx & 7) << 4;
                uint32_t so = (uint32_t)row * SMS + chb;
                size_t go = (size_t)row * ldb + kb + chb;
                cp_async16(st + so, gAh + go);
                if (NSPLIT >= 2) cp_async16(st + OFF_AL + so, gAl + go);
            }
#pragma unroll
            for (int it = 0; it < 4; it++) {
                int idx = it * 256 + tid;
                int row = idx >> 3;
                uint32_t chb = (uint32_t)(idx & 7) << 4;
                uint32_t so = (uint32_t)row * SMS + chb;
                size_t go = (size_t)row * ldb + kb + chb;
                cp_async16(st + OFF_B + so, gBh + go);
            }
            cp_commit();
        };

        // prologue: NST-1 chunks in flight (nch >= 12 always here)
#pragma unroll
        for (int p = 0; p < NST - 1; p++) issue(p);
        cp_wait<NST - 2>();        // chunk 0 arrived
        __syncthreads();

        for (int kt = 0; kt < nch; kt++) {
            // writes stage (kt-1)%NST, whose readers all synced last iteration
            if (kt + NST - 1 < nch) issue(kt + NST - 1);

            const uint32_t st = sbase + (uint32_t)(kt % NST) * ST_SZ;
#pragma unroll
            for (int kk = 0; kk < 4; kk++) {
                const uint32_t kkB = (uint32_t)kk << 5;   // 16 elems = 32 bytes
                uint32_t bh[4][4];
#pragma unroll
                for (int np = 0; np < 4; np++)
                    ldsm4(bh[np], st + OFF_B + bOff + (uint32_t)np * 16 * SMS + kkB);
#pragma unroll
                for (int mi = 0; mi < 4; mi++) {
                    uint32_t ah[4], al[4];
                    ldsm4(ah, st + aOff + (uint32_t)mi * 16 * SMS + kkB);
                    if (NSPLIT >= 2)
                        ldsm4(al, st + OFF_AL + aOff + (uint32_t)mi * 16 * SMS + kkB);
#pragma unroll
                    for (int ni = 0; ni < 8; ni++) {
                        const int np = ni >> 1, hh = (ni & 1) << 1;
                        mma_f16(acc[mi][ni], ah, bh[np][hh], bh[np][hh + 1]);
                        if (NSPLIT >= 2)
                            mma_f16(acc[mi][ni], al, bh[np][hh], bh[np][hh + 1]);
                    }
                }
            }

            if (kt + 1 < nch) {
                // ensure chunk kt+1 complete (exact waits at the tail)
                const int rem = nch - kt - 2;   // max groups allowed pending
                if (rem >= NST - 2)      cp_wait<NST - 2>();
                else if (NST > 2 && rem >= 1) cp_wait<1>();
                else                     cp_wait<0>();
                __syncthreads();
            }
        }

        if (!DO_S) {
            // ---- standard epilogue ----
#pragma unroll
            for (int mi = 0; mi < 4; mi++) {
#pragma unroll
                for (int ni = 0; ni < 8; ni++) {
                    const int col = n0 + wn * 64 + ni * 8 + ((lid & 3) << 1);
#pragma unroll
                    for (int half = 0; half < 2; half++) {
                        const int row = m0 + wm * 64 + mi * 16 + (lid >> 2) + half * 8;
                        float v0 = acc[mi][ni][half * 2 + 0];
                        float v1 = acc[mi][ni][half * 2 + 1];
                        if (bias) { v0 += bias[col]; v1 += bias[col + 1]; }
                        if (doRelu) { v0 = fmaxf(v0, 0.f); v1 = fmaxf(v1, 0.f); }
                        if (resid) {
                            float2 r = *(const float2*)(resid + (size_t)row * N + col);
                            v0 += r.x; v1 += r.y;
                        }
                        if (C) {
                            float2 w; w.x = v0; w.y = v1;
                            *(float2*)(C + (size_t)row * N + col) = w;
                        }
                        if (CHi) {
                            __half h0, l0, h1, l1;
                            split_f16(v0, h0, l0);
                            split_f16(v1, h1, l1);
                            uint32_t ph = (uint32_t)__half_as_ushort(h0) |
                                          ((uint32_t)__half_as_ushort(h1) << 16);
                            *(uint32_t*)(CHi + (size_t)row * N + col) = ph;
                            if (CLo) {
                                uint32_t pl = (uint32_t)__half_as_ushort(l0) |
                                              ((uint32_t)__half_as_ushort(l1) << 16);
                                *(uint32_t*)(CLo + (size_t)row * N + col) = pl;
                            }
                        }
                    }
                }
            }
        } else {
            // ---- fused online-softmax partial epilogue (S GEMM) ----
            float* shm = (float*)smem;                 // [256]
            float* shs = (float*)(smem + 1024);        // [256]
            int*   shi = (int*)(smem + 2048);          // [256]
            __syncthreads();

#pragma unroll
            for (int mi = 0; mi < 4; mi++) {
#pragma unroll
                for (int half = 0; half < 2; half++) {
                    float lm = -3.4e38f;
                    int   li = 0x7fffffff;
#pragma unroll
                    for (int ni = 0; ni < 8; ni++) {
#pragma unroll
                        for (int q = 0; q < 2; q++) {
                            float v = acc[mi][ni][half * 2 + q];
                            if (v > lm) {
                                lm = v;
                                li = n0 + wn * 64 + ni * 8 + ((lid & 3) << 1) + q;
                            }
                        }
                    }
                    float ls = 0.f;
#pragma unroll
                    for (int ni = 0; ni < 8; ni++) {
#pragma unroll
                        for (int q = 0; q < 2; q++)
                            ls += __expf(acc[mi][ni][half * 2 + q] - lm);
                    }
#pragma unroll
                    for (int d = 1; d < 4; d <<= 1) {
                        float om = __shfl_xor_sync(0xffffffff, lm, d);
                        float os = __shfl_xor_sync(0xffffffff, ls, d);
                        int   oi = __shfl_xor_sync(0xffffffff, li, d);
                        olmerge(lm, ls, li, om, os, oi);
                    }
                    int r = wm * 64 + mi * 16 + (lid >> 2) + half * 8;  // 0..255
                    if ((lid & 3) == 0) {
                        if (wn == 1) { shm[r] = lm; shs[r] = ls; shi[r] = li; }
                    }
                    acc[mi][0][half * 2] = lm;   // reuse acc as scratch
                    acc[mi][1][half * 2] = ls;
                    acc[mi][2][half * 2] = __int_as_float(li);
                }
            }
            __syncthreads();
            if (wn == 0 && (lid & 3) == 0) {
#pragma unroll
                for (int mi = 0; mi < 4; mi++) {
#pragma unroll
                    for (int half = 0; half < 2; half++) {
                        int r = wm * 64 + mi * 16 + (lid >> 2) + half * 8;
                        float lm = acc[mi][0][half * 2];
                        float ls = acc[mi][1][half * 2];
                        int   li = __float_as_int(acc[mi][2][half * 2]);
                        olmerge(lm, ls, li, shm[r], shs[r], shi[r]);
                        size_t po = (size_t)(m0 + r) * NTILE_S + bx;
                        g_pM[po] = lm;
                        g_pS[po] = ls;
                        g_pI[po] = li;
                    }
                }
            }
        }
        __syncthreads();   // protect smem stages before next tile's prologue
    }
}

// ===========================================================================
// LN2 + normalize; write pred (f32) and PN fp16.
// ===========================================================================
__global__ void ln2_norm_kernel(const float* __restrict__ P,
                                const float* __restrict__ g,
                                const float* __restrict__ b,
                                float* __restrict__ pred)
{
    int row = blockIdx.x, tid = threadIdx.x;
    const float* pr = P + (size_t)row * OUTD;
    float v[3];
    float s = 0.f, ss = 0.f;
#pragma unroll
    for (int i = 0; i < 3; i++) {
        int j = tid + i * 256;
        v[i] = pr[j];
        s += v[i]; ss += v[i] * v[i];
    }
    __shared__ float sh[256], sh2[256];
    sh[tid] = s; sh2[tid] = ss;
    __syncthreads();
    for (int o = 128; o > 0; o >>= 1) {
        if (tid < o) { sh[tid] += sh[tid + o]; sh2[tid] += sh2[tid + o]; }
        __syncthreads();
    }
    __shared__ float smean, srstd;
    if (tid == 0) {
        float m = sh[0] / (float)OUTD;
        float var = sh2[0] / (float)OUTD - m * m;
        smean = m; srstd = rsqrtf(var + LN_EPS);
    }
    __syncthreads();
    float t[3];
    float tss = 0.f;
#pragma unroll
    for (int i = 0; i < 3; i++) {
        int j = tid + i * 256;
        t[i] = (v[i] - smean) * srstd * g[j] + b[j];
        tss += t[i] * t[i];
    }
    __syncthreads();
    sh[tid] = tss;
    __syncthreads();
    for (int o = 128; o > 0; o >>= 1) {
        if (tid < o) sh[tid] += sh[tid + o];
        __syncthreads();
    }
    __shared__ float sinv;
    if (tid == 0) sinv = 1.f / sqrtf(sh[0]);
    __syncthreads();
    float* pw = pred + (size_t)row * OUTD;
#pragma unroll
    for (int i = 0; i < 3; i++) {
        int j = tid + i * 256;
        pw[j] = t[i];
        g_PN16[(size_t)row * OUTD + j] = __float2half_rn(t[i] * sinv);
    }
}

__global__ void ynorm_kernel(const float* __restrict__ y)
{
    int row = blockIdx.x, tid = threadIdx.x;
    const float* yr = y + (size_t)row * OUTD;
    float v[3];
    float ss = 0.f;
#pragma unroll
    for (int i = 0; i < 3; i++) {
        int j = tid + i * 256;
        v[i] = yr[j];
        ss += v[i] * v[i];
    }
    __shared__ float sh[256];
    sh[tid] = ss;
    __syncthreads();
    for (int o = 128; o > 0; o >>= 1) {
        if (tid < o) sh[tid] += sh[tid + o];
        __syncthreads();
    }
    __shared__ float sinv;
    if (tid == 0) sinv = 1.f / sqrtf(sh[0]);
    __syncthreads();
#pragma unroll
    for (int i = 0; i < 3; i++) {
        int j = tid + i * 256;
        g_YN16[(size_t)row * OUTD + j] = __float2half_rn(v[i] * sinv);
    }
}

// ===========================================================================
// merge_S: per row, merge NTILE_S partials -> lse, argmax; diag dot; loss/acc.
// ===========================================================================
__global__ void merge_S_kernel()
{
    int row = blockIdx.x, tid = threadIdx.x;   // 128 threads
    __shared__ float shm[128], shs[128];
    __shared__ int   shidx[128];

    float m = -3.4e38f, s = 0.f;
    int   ix = 0x7fffffff;
    if (tid < NTILE_S) {
        size_t po = (size_t)row * NTILE_S + tid;
        m = g_pM[po]; s = g_pS[po]; ix = g_pI[po];
    }
    shm[tid] = m; shs[tid] = s; shidx[tid] = ix;
    __syncthreads();
    for (int o = 64; o > 0; o >>= 1) {
        if (tid < o) {
            float lm = shm[tid], ls = shs[tid];
            int   li = shidx[tid];
            olmerge(lm, ls, li, shm[tid + o], shs[tid + o], shidx[tid + o]);
            shm[tid] = lm; shs[tid] = ls; shidx[tid] = li;
        }
        __syncthreads();
    }
    __shared__ float s_lse;
    __shared__ int   s_arg;
    if (tid == 0) {
        s_lse = shm[0] + __logf(shs[0]);
        s_arg = shidx[0];
    }
    __syncthreads();

    // diagonal S_ii = dot(PN16[row], YN16[row])
    float d = 0.f;
    const __half* pr = g_PN16 + (size_t)row * OUTD;
    const __half* yr = g_YN16 + (size_t)row * OUTD;
#pragma unroll
    for (int i = 0; i < 6; i++) {
        int j = tid + i * 128;
        d += __half2float(pr[j]) * __half2float(yr[j]);
    }
    shm[tid] = d;
    __syncthreads();
    for (int o = 64; o > 0; o >>= 1) {
        if (tid < o) shm[tid] += shm[tid + o];
        __syncthreads();
    }
    if (tid == 0) {
        double contrib = (double)s_lse - (double)shm[0];
        atomicAdd(&g_loss, contrib);
        if (s_arg == row) atomicAdd(&g_correct, 1);
    }
}

__global__ void finalize_kernel(float* __restrict__ out, int out_size)
{
    const int NP = BSZ * OUTD;
    if (out_size >= NP + 2) {
        out[NP]     = (float)g_loss;
        out[NP + 1] = (float)g_correct / (float)BSZ;
    }
}

// ===========================================================================
extern "C" void kernel_launch(void* const* d_in, const int* in_sizes, int n_in,
                              void* d_out, int out_size)
{
    const float* inp  = (const float*)d_in[0];
    const float* y    = (const float*)d_in[1];
    const float* ln1g = (const float*)d_in[2];
    const float* ln1b = (const float*)d_in[3];
    const float* W1   = (const float*)d_in[4];
    const float* b1   = (const float*)d_in[5];
    const float* Wa   = (const float*)d_in[6];
    const float* ba   = (const float*)d_in[7];
    const float* Wb   = (const float*)d_in[8];
    const float* bb   = (const float*)d_in[9];
    const float* W2   = (const float*)d_in[10];
    const float* b2   = (const float*)d_in[11];
    const float* ln2g = (const float*)d_in[12];
    const float* ln2b = (const float*)d_in[13];
    float* out = (float*)d_out;

    static int smem_cfg_done = 0;
    if (!smem_cfg_done) {
        cudaFuncSetAttribute((const void*)tc_gemm<1, false>,
                             cudaFuncAttributeMaxDynamicSharedMemorySize, GEMM_SMEM_BYTES);
        cudaFuncSetAttribute((const void*)tc_gemm<2, false>,
                             cudaFuncAttributeMaxDynamicSharedMemorySize, GEMM_SMEM_BYTES);
        cudaFuncSetAttribute((const void*)tc_gemm<1, true>,
                             cudaFuncAttributeMaxDynamicSharedMemorySize, GEMM_SMEM_BYTES);
        smem_cfg_done = 1;
    }

    float *H, *P;
    cudaGetSymbolAddress((void**)&H, g_H);
    cudaGetSymbolAddress((void**)&P, g_P);
    __half *A1h, *Hh, *Hl, *Th, *PN16, *YN16;
    __half *W1h, *Wah, *Wbh, *W2h;
    cudaGetSymbolAddress((void**)&A1h, g_A1h);
    cudaGetSymbolAddress((void**)&Hh,  g_Hh);
    cudaGetSymbolAddress((void**)&Hl,  g_Hl);
    cudaGetSymbolAddress((void**)&Th,  g_Th);
    cudaGetSymbolAddress((void**)&PN16, g_PN16);
    cudaGetSymbolAddress((void**)&YN16, g_YN16);
    cudaGetSymbolAddress((void**)&W1h, g_W1h);
    cudaGetSymbolAddress((void**)&Wah, g_Wah);
    cudaGetSymbolAddress((void**)&Wbh, g_Wbh);
    cudaGetSymbolAddress((void**)&W2h, g_W2h);

    const int NSM = 152;
    auto grid_for = [&](int M, int N) {
        int nt = (M >> 8) * (N >> 7);
        return nt < NSM ? nt : NSM;
    };

    tsplit_all_kernel<<<dim3(INPD / 32, HIDD / 32, 4), dim3(32, 8)>>>(W1, Wa, Wb, W2);
    ln1_split_kernel<<<BSZ, 256>>>(inp, ln1g, ln1b);

    // H = LN1(inp) @ W1 + b1 — pure fp16 (1 MMA, 4-stage); f32 H + Hh
    tc_gemm<1, false><<<grid_for(BSZ, HIDD), 256, GEMM_SMEM_BYTES>>>(
        A1h, nullptr, W1h, b1, nullptr, H, Hh, nullptr, BSZ, HIDD, INPD, 0);

    // residual blocks — pure fp16 (1 MMA, 4-stage)
    tc_gemm<1, false><<<grid_for(BSZ, HIDD), 256, GEMM_SMEM_BYTES>>>(
        Hh, nullptr, Wah, ba, nullptr, nullptr, Th, nullptr, BSZ, HIDD, HIDD, 1);
    tc_gemm<1, false><<<grid_for(BSZ, HIDD), 256, GEMM_SMEM_BYTES>>>(
        Th, nullptr, Wbh, bb, H, H, Hh, nullptr, BSZ, HIDD, HIDD, 1);
    tc_gemm<1, false><<<grid_for(BSZ, HIDD), 256, GEMM_SMEM_BYTES>>>(
        Hh, nullptr, Wah, ba, nullptr, nullptr, Th, nullptr, BSZ, HIDD, HIDD, 1);
    tc_gemm<1, false><<<grid_for(BSZ, HIDD), 256, GEMM_SMEM_BYTES>>>(
        Th, nullptr, Wbh, bb, H, H, Hh, Hl, BSZ, HIDD, HIDD, 1);

    // P = H @ W2 + b2 — fp16 A-pair x W2-single (2 MMAs, 2-stage)
    tc_gemm<2, false><<<grid_for(BSZ, OUTD), 256, GEMM_SMEM_BYTES>>>(
        Hh, Hl, W2h, b2, nullptr, P, nullptr, nullptr, BSZ, OUTD, HIDD, 0);

    ln2_norm_kernel<<<BSZ, 256>>>(P, ln2g, ln2b, out);
    ynorm_kernel<<<BSZ, 256>>>(y);

    // S = PN @ YN^T — fp16 single (4-stage), fused online-softmax epilogue
    tc_gemm<1, true><<<grid_for(BSZ, BSZ), 256, GEMM_SMEM_BYTES>>>(
        PN16, nullptr, YN16, nullptr, nullptr, nullptr, nullptr, nullptr,
        BSZ, BSZ, OUTD, 0);

    merge_S_kernel<<<BSZ, 128>>>();
    finalize_kernel<<<1, 1>>>(out, out_size);
}

// round 16
// speedup vs baseline: 1.1043x; 1.1043x over previous
#include <cuda_runtime.h>
#include <cuda_bf16.h>
#include <cuda_fp16.h>
#include <math.h>
#include <stdint.h>

#define BSZ  8192
#define INPD 3072
#define HIDD 1024
#define OUTD 768
#define LN_EPS 1e-5f
#define NTILE_S 64            // 8192 / 128 column tiles in the S GEMM

// ===========================================================================
// Scratch (__device__ globals; no allocations allowed anywhere).
// ===========================================================================
__device__ float g_P[(size_t)BSZ * OUTD];
__device__ double g_loss;
__device__ int    g_correct;

// per-(row, col-tile) online-softmax partials for S
__device__ float g_pM[(size_t)BSZ * NTILE_S];
__device__ float g_pS[(size_t)BSZ * NTILE_S];
__device__ int   g_pI[(size_t)BSZ * NTILE_S];

// fp16 operand buffers (activations)
__device__ __half g_A1h[(size_t)BSZ * INPD];
__device__ float  g_H[(size_t)BSZ * HIDD];       // f32 residual stream
__device__ __half g_Hh[(size_t)BSZ * HIDD];
__device__ __half g_Hl[(size_t)BSZ * HIDD];
__device__ __half g_Th[(size_t)BSZ * HIDD];
// fp16 operands for the S GEMM
__device__ __half g_PN16[(size_t)BSZ * OUTD];
__device__ __half g_YN16[(size_t)BSZ * OUTD];
// transposed weights: [N rows][K cols], K-major, fp16
__device__ __half g_W1h[(size_t)HIDD * INPD];
__device__ __half g_Wah[(size_t)HIDD * HIDD];
__device__ __half g_Wbh[(size_t)HIDD * HIDD];
__device__ __half g_W2h[(size_t)OUTD * HIDD];

// ===========================================================================
// Helpers (base compute_103 features only: mma.sync / ldmatrix / cp.async)
// ===========================================================================
__device__ __forceinline__ uint32_t smem_to_u32(const void* p) {
    uint32_t a;
    asm("{ .reg .u64 t; cvta.to.shared.u64 t, %1; cvt.u32.u64 %0, t; }"
        : "=r"(a) : "l"(p));
    return a;
}

__device__ __forceinline__ void cp_async16(uint32_t saddr, const void* gaddr) {
    asm volatile("cp.async.cg.shared.global [%0], [%1], 16;"
                 :: "r"(saddr), "l"(gaddr) : "memory");
}
__device__ __forceinline__ void cp_commit() {
    asm volatile("cp.async.commit_group;" ::: "memory");
}
template <int N>
__device__ __forceinline__ void cp_wait() {
    asm volatile("cp.async.wait_group %0;" :: "n"(N) : "memory");
}

__device__ __forceinline__ void ldsm4(uint32_t* r, uint32_t addr) {
    asm volatile("ldmatrix.sync.aligned.m8n8.x4.shared.b16 {%0,%1,%2,%3}, [%4];"
                 : "=r"(r[0]), "=r"(r[1]), "=r"(r[2]), "=r"(r[3]) : "r"(addr));
}

__device__ __forceinline__ void mma_f16(float* c, const uint32_t* a,
                                        uint32_t b0, uint32_t b1) {
    asm volatile(
        "mma.sync.aligned.m16n8k16.row.col.f32.f16.f16.f32 "
        "{%0,%1,%2,%3}, {%4,%5,%6,%7}, {%8,%9}, {%0,%1,%2,%3};"
        : "+f"(c[0]), "+f"(c[1]), "+f"(c[2]), "+f"(c[3])
        : "r"(a[0]), "r"(a[1]), "r"(a[2]), "r"(a[3]), "r"(b0), "r"(b1));
}

__device__ __forceinline__ void split_f16(float v, __half& h, __half& l) {
    h = __float2half_rn(v);
    l = __float2half_rn(v - __half2float(h));
}

// online-softmax pairwise merge (m, s, first-max index)
__device__ __forceinline__ void olmerge(float& m1, float& s1, int& i1,
                                        float m2, float s2, int i2) {
    if (m2 > m1)      { s1 = s2 + s1 * __expf(m1 - m2); m1 = m2; i1 = i2; }
    else if (m2 < m1) { s1 = s1 + s2 * __expf(m2 - m1); }
    else              { s1 = s1 + s2; i1 = min(i1, i2); }
}

// ===========================================================================
// tsplit_all: transpose + fp16-quantize all four weights in ONE launch.
// ===========================================================================
__global__ void tsplit_all_kernel(const float* __restrict__ W1,
                                  const float* __restrict__ Wa,
                                  const float* __restrict__ Wb,
                                  const float* __restrict__ W2)
{
    const float* W; __half* TH; int K, N;
    switch (blockIdx.z) {
        case 0: W = W1; TH = g_W1h; K = INPD; N = HIDD; break;
        case 1: W = Wa; TH = g_Wah; K = HIDD; N = HIDD; break;
        case 2: W = Wb; TH = g_Wbh; K = HIDD; N = HIDD; break;
        default: W = W2; TH = g_W2h; K = HIDD; N = OUTD; break;
    }
    int k0 = blockIdx.x * 32, n0 = blockIdx.y * 32;
    if (k0 >= K || n0 >= N) return;

    __shared__ float t[32][33];
    int tx = threadIdx.x, ty = threadIdx.y;   // 32 x 8
#pragma unroll
    for (int i = 0; i < 32; i += 8)
        t[ty + i][tx] = W[(size_t)(k0 + ty + i) * N + n0 + tx];
    __syncthreads();
#pragma unroll
    for (int i = 0; i < 32; i += 8) {
        float v = t[tx][ty + i];
        size_t o = (size_t)(n0 + ty + i) * K + k0 + tx;
        TH[o] = __float2half_rn(v);
    }
}

// LN1 -> fp16 (also zeroes the loss accumulators from block 0).
__global__ void ln1_split_kernel(const float* __restrict__ x,
                                 const float* __restrict__ g,
                                 const float* __restrict__ b)
{
    int row = blockIdx.x, tid = threadIdx.x;
    if (row == 0 && tid == 0) { g_loss = 0.0; g_correct = 0; }
    const float* xr = x + (size_t)row * INPD;
    float v[12];
    float s = 0.f, ss = 0.f;
#pragma unroll
    for (int i = 0; i < 12; i++) {
        int j = tid + i * 256;
        v[i] = xr[j];
        s += v[i]; ss += v[i] * v[i];
    }
    __shared__ float sh[256], sh2[256];
    sh[tid] = s; sh2[tid] = ss;
    __syncthreads();
    for (int o = 128; o > 0; o >>= 1) {
        if (tid < o) { sh[tid] += sh[tid + o]; sh2[tid] += sh2[tid + o]; }
        __syncthreads();
    }
    __shared__ float sm, sr;
    if (tid == 0) {
        float m = sh[0] / (float)INPD;
        float var = sh2[0] / (float)INPD - m * m;
        sm = m; sr = rsqrtf(var + LN_EPS);
    }
    __syncthreads();
    float m = sm, r = sr;
#pragma unroll
    for (int i = 0; i < 12; i++) {
        int j = tid + i * 256;
        float t = (v[i] - m) * r * g[j] + b[j];
        g_A1h[(size_t)row * INPD + j] = __float2half_rn(t);
    }
}

// ===========================================================================
// Persistent tensor-core GEMM via fp16 mma.sync: C[M,N] = ep(A @ B^T)
// Tile 128x128, 256 threads, 8 warps (4m x 2n), warp tile 32x64, k-chunk 64.
// 2 CTAs/SM (occupancy-driven): acc = 64 regs/thread.
// NSPLIT=2: A pair x B single, 2 MMAs, 2-stage ring (55296 B/stage).
// NSPLIT=1: A single x B single, 1 MMA, 3-stage ring (36864 B/stage).
// DO_S: emit per-(row, col-tile) online-softmax partials instead of storing C.
// ===========================================================================
#define SMS    144                      // smem row stride in bytes (128 + 16 pad)
#define T_BUF  (128 * SMS)              // 18432 (one 128x64 fp16 buffer)
#define GEMM_SMEM_BYTES 110592          // 3 * (2*T_BUF) == 2 * (3*T_BUF)

template <int NSPLIT, bool DO_S>
__global__ void __launch_bounds__(256, 2)
tc_gemm(const __half* __restrict__ AHi, const __half* __restrict__ ALo,
        const __half* __restrict__ BHi,
        const float* __restrict__ bias, const float* __restrict__ resid,
        float* __restrict__ C,
        __half* __restrict__ CHi, __half* __restrict__ CLo,
        int M, int N, int K, int doRelu)
{
    constexpr int NST    = (NSPLIT >= 2) ? 2 : 3;
    constexpr int OFF_AL = T_BUF;                                  // NSPLIT=2 only
    constexpr int OFF_B  = (NSPLIT >= 2) ? 2 * T_BUF : T_BUF;
    constexpr int ST_SZ  = (NSPLIT >= 2) ? 3 * T_BUF : 2 * T_BUF;

    extern __shared__ char smem[];
    const uint32_t sbase = smem_to_u32(smem);
    const int tid = threadIdx.x;
    const int wid = tid >> 5, lid = tid & 31;
    const int wm = wid & 3, wn = wid >> 2;     // 4m x 2n warp grid (32x64 tiles)
    const size_t ldb = (size_t)K * 2;          // bytes per row
    const int nch = K >> 6;                    // k-chunks of 64
    const int ntN = N >> 7, ntM = M >> 7;
    const int ntotal = ntN * ntM;

    const uint32_t aOff = (uint32_t)((wm * 32 + (lid & 15)) * SMS) + ((lid >> 4) << 4);
    const uint32_t bOff = (uint32_t)((wn * 64 + (lid & 7) + ((lid >> 4) << 3)) * SMS)
                        + (((lid >> 3) & 1) << 4);

    for (int t = blockIdx.x; t < ntotal; t += gridDim.x) {
        const int bx = t % ntN, by = t / ntN;
        const int m0 = by * 128, n0 = bx * 128;
        const char* gAh = (const char*)AHi + (size_t)m0 * ldb;
        const char* gAl = (const char*)ALo + (size_t)m0 * ldb;
        const char* gBh = (const char*)BHi + (size_t)n0 * ldb;

        float acc[2][8][4];
#pragma unroll
        for (int i = 0; i < 2; i++)
#pragma unroll
            for (int j = 0; j < 8; j++)
#pragma unroll
                for (int q = 0; q < 4; q++) acc[i][j][q] = 0.f;

        auto issue = [&](int kt) {
            const uint32_t st = sbase + (uint32_t)(kt % NST) * ST_SZ;
            const size_t kb = (size_t)kt << 7;     // 64 elems = 128 bytes
            // A and B: each 128 rows x 8 chunks = 1024; 4 iters of 256 threads
#pragma unroll
            for (int it = 0; it < 4; it++) {
                int idx = it * 256 + tid;
                int row = idx >> 3;
                uint32_t chb = (uint32_t)(idx & 7) << 4;
                uint32_t so = (uint32_t)row * SMS + chb;
                size_t go = (size_t)row * ldb + kb + chb;
                cp_async16(st + so, gAh + go);
                if (NSPLIT >= 2) cp_async16(st + OFF_AL + so, gAl + go);
                cp_async16(st + OFF_B + so, gBh + go);
            }
            cp_commit();
        };

        // prologue: NST-1 chunks in flight (nch >= 12 here)
#pragma unroll
        for (int p = 0; p < NST - 1; p++) issue(p);
        cp_wait<NST - 2>();        // chunk 0 arrived
        __syncthreads();

        for (int kt = 0; kt < nch; kt++) {
            if (kt + NST - 1 < nch) issue(kt + NST - 1);

            const uint32_t st = sbase + (uint32_t)(kt % NST) * ST_SZ;
#pragma unroll
            for (int kk = 0; kk < 4; kk++) {
                const uint32_t kkB = (uint32_t)kk << 5;   // 16 elems = 32 bytes
                uint32_t bh[4][4];
#pragma unroll
                for (int np = 0; np < 4; np++)
                    ldsm4(bh[np], st + OFF_B + bOff + (uint32_t)np * 16 * SMS + kkB);
#pragma unroll
                for (int mi = 0; mi < 2; mi++) {
                    uint32_t ah[4], al[4];
                    ldsm4(ah, st + aOff + (uint32_t)mi * 16 * SMS + kkB);
                    if (NSPLIT >= 2)
                        ldsm4(al, st + OFF_AL + aOff + (uint32_t)mi * 16 * SMS + kkB);
#pragma unroll
                    for (int ni = 0; ni < 8; ni++) {
                        const int np = ni >> 1, hh = (ni & 1) << 1;
                        mma_f16(acc[mi][ni], ah, bh[np][hh], bh[np][hh + 1]);
                        if (NSPLIT >= 2)
                            mma_f16(acc[mi][ni], al, bh[np][hh], bh[np][hh + 1]);
                    }
                }
            }

            if (kt + 1 < nch) {
                const int rem = nch - kt - 2;   // groups allowed pending
                if (rem >= NST - 2)           cp_wait<NST - 2>();
                else if (NST > 2 && rem >= 1) cp_wait<1>();
                else                          cp_wait<0>();
                __syncthreads();
            }
        }

        if (!DO_S) {
            // ---- standard epilogue ----
#pragma unroll
            for (int mi = 0; mi < 2; mi++) {
#pragma unroll
                for (int ni = 0; ni < 8; ni++) {
                    const int col = n0 + wn * 64 + ni * 8 + ((lid & 3) << 1);
#pragma unroll
                    for (int half = 0; half < 2; half++) {
                        const int row = m0 + wm * 32 + mi * 16 + (lid >> 2) + half * 8;
                        float v0 = acc[mi][ni][half * 2 + 0];
                        float v1 = acc[mi][ni][half * 2 + 1];
                        if (bias) { v0 += bias[col]; v1 += bias[col + 1]; }
                        if (doRelu) { v0 = fmaxf(v0, 0.f); v1 = fmaxf(v1, 0.f); }
                        if (resid) {
                            float2 r = *(const float2*)(resid + (size_t)row * N + col);
                            v0 += r.x; v1 += r.y;
                        }
                        if (C) {
                            float2 w; w.x = v0; w.y = v1;
                            *(float2*)(C + (size_t)row * N + col) = w;
                        }
                        if (CHi) {
                            __half h0, l0, h1, l1;
                            split_f16(v0, h0, l0);
                            split_f16(v1, h1, l1);
                            uint32_t ph = (uint32_t)__half_as_ushort(h0) |
                                          ((uint32_t)__half_as_ushort(h1) << 16);
                            *(uint32_t*)(CHi + (size_t)row * N + col) = ph;
                            if (CLo) {
                                uint32_t pl = (uint32_t)__half_as_ushort(l0) |
                                              ((uint32_t)__half_as_ushort(l1) << 16);
                                *(uint32_t*)(CLo + (size_t)row * N + col) = pl;
                            }
                        }
                    }
                }
            }
        } else {
            // ---- fused online-softmax partial epilogue (S GEMM) ----
            float* shm = (float*)smem;                 // [128]
            float* shs = (float*)(smem + 512);         // [128]
            int*   shi = (int*)(smem + 1024);          // [128]
            __syncthreads();

#pragma unroll
            for (int mi = 0; mi < 2; mi++) {
#pragma unroll
                for (int half = 0; half < 2; half++) {
                    float lm = -3.4e38f;
                    int   li = 0x7fffffff;
#pragma unroll
                    for (int ni = 0; ni < 8; ni++) {
#pragma unroll
                        for (int q = 0; q < 2; q++) {
                            float v = acc[mi][ni][half * 2 + q];
                            if (v > lm) {
                                lm = v;
                                li = n0 + wn * 64 + ni * 8 + ((lid & 3) << 1) + q;
                            }
                        }
                    }
                    float ls = 0.f;
#pragma unroll
                    for (int ni = 0; ni < 8; ni++) {
#pragma unroll
                        for (int q = 0; q < 2; q++)
                            ls += __expf(acc[mi][ni][half * 2 + q] - lm);
                    }
#pragma unroll
                    for (int d = 1; d < 4; d <<= 1) {
                        float om = __shfl_xor_sync(0xffffffff, lm, d);
                        float os = __shfl_xor_sync(0xffffffff, ls, d);
                        int   oi = __shfl_xor_sync(0xffffffff, li, d);
                        olmerge(lm, ls, li, om, os, oi);
                    }
                    int r = wm * 32 + mi * 16 + (lid >> 2) + half * 8;  // 0..127
                    if ((lid & 3) == 0) {
                        if (wn == 1) { shm[r] = lm; shs[r] = ls; shi[r] = li; }
                    }
                    acc[mi][0][half * 2] = lm;   // reuse acc as scratch
                    acc[mi][1][half * 2] = ls;
                    acc[mi][2][half * 2] = __int_as_float(li);
                }
            }
            __syncthreads();
            if (wn == 0 && (lid & 3) == 0) {
#pragma unroll
                for (int mi = 0; mi < 2; mi++) {
#pragma unroll
                    for (int half = 0; half < 2; half++) {
                        int r = wm * 32 + mi * 16 + (lid >> 2) + half * 8;
                        float lm = acc[mi][0][half * 2];
                        float ls = acc[mi][1][half * 2];
                        int   li = __float_as_int(acc[mi][2][half * 2]);
                        olmerge(lm, ls, li, shm[r], shs[r], shi[r]);
                        size_t po = (size_t)(m0 + r) * NTILE_S + bx;
                        g_pM[po] = lm;
                        g_pS[po] = ls;
                        g_pI[po] = li;
                    }
                }
            }
        }
        __syncthreads();   // protect smem stages before next tile's prologue
    }
}

// ===========================================================================
// LN2 + normalize; write pred (f32) and PN fp16.
// ===========================================================================
__global__ void ln2_norm_kernel(const float* __restrict__ P,
                                const float* __restrict__ g,
                                const float* __restrict__ b,
                                float* __restrict__ pred)
{
    int row = blockIdx.x, tid = threadIdx.x;
    const float* pr = P + (size_t)row * OUTD;
    float v[3];
    float s = 0.f, ss = 0.f;
#pragma unroll
    for (int i = 0; i < 3; i++) {
        int j = tid + i * 256;
        v[i] = pr[j];
        s += v[i]; ss += v[i] * v[i];
    }
    __shared__ float sh[256], sh2[256];
    sh[tid] = s; sh2[tid] = ss;
    __syncthreads();
    for (int o = 128; o > 0; o >>= 1) {
        if (tid < o) { sh[tid] += sh[tid + o]; sh2[tid] += sh2[tid + o]; }
        __syncthreads();
    }
    __shared__ float smean, srstd;
    if (tid == 0) {
        float m = sh[0] / (float)OUTD;
        float var = sh2[0] / (float)OUTD - m * m;
        smean = m; srstd = rsqrtf(var + LN_EPS);
    }
    __syncthreads();
    float t[3];
    float tss = 0.f;
#pragma unroll
    for (int i = 0; i < 3; i++) {
        int j = tid + i * 256;
        t[i] = (v[i] - smean) * srstd * g[j] + b[j];
        tss += t[i] * t[i];
    }
    __syncthreads();
    sh[tid] = tss;
    __syncthreads();
    for (int o = 128; o > 0; o >>= 1) {
        if (tid < o) sh[tid] += sh[tid + o];
        __syncthreads();
    }
    __shared__ float sinv;
    if (tid == 0) sinv = 1.f / sqrtf(sh[0]);
    __syncthreads();
    float* pw = pred + (size_t)row * OUTD;
#pragma unroll
    for (int i = 0; i < 3; i++) {
        int j = tid + i * 256;
        pw[j] = t[i];
        g_PN16[(size_t)row * OUTD + j] = __float2half_rn(t[i] * sinv);
    }
}

__global__ void ynorm_kernel(const float* __restrict__ y)
{
    int row = blockIdx.x, tid = threadIdx.x;
    const float* yr = y + (size_t)row * OUTD;
    float v[3];
    float ss = 0.f;
#pragma unroll
    for (int i = 0; i < 3; i++) {
        int j = tid + i * 256;
        v[i] = yr[j];
        ss += v[i] * v[i];
    }
    __shared__ float sh[256];
    sh[tid] = ss;
    __syncthreads();
    for (int o = 128; o > 0; o >>= 1) {
        if (tid < o) sh[tid] += sh[tid + o];
        __syncthreads();
    }
    __shared__ float sinv;
    if (tid == 0) sinv = 1.f / sqrtf(sh[0]);
    __syncthreads();
#pragma unroll
    for (int i = 0; i < 3; i++) {
        int j = tid + i * 256;
        g_YN16[(size_t)row * OUTD + j] = __float2half_rn(v[i] * sinv);
    }
}

// ===========================================================================
// merge_S: per row, merge NTILE_S partials -> lse, argmax; diag dot; loss/acc.
// ===========================================================================
__global__ void merge_S_kernel()
{
    int row = blockIdx.x, tid = threadIdx.x;   // 128 threads
    __shared__ float shm[128], shs[128];
    __shared__ int   shidx[128];

    float m = -3.4e38f, s = 0.f;
    int   ix = 0x7fffffff;
    if (tid < NTILE_S) {
        size_t po = (size_t)row * NTILE_S + tid;
        m = g_pM[po]; s = g_pS[po]; ix = g_pI[po];
    }
    shm[tid] = m; shs[tid] = s; shidx[tid] = ix;
    __syncthreads();
    for (int o = 64; o > 0; o >>= 1) {
        if (tid < o) {
            float lm = shm[tid], ls = shs[tid];
            int   li = shidx[tid];
            olmerge(lm, ls, li, shm[tid + o], shs[tid + o], shidx[tid + o]);
            shm[tid] = lm; shs[tid] = ls; shidx[tid] = li;
        }
        __syncthreads();
    }
    __shared__ float s_lse;
    __shared__ int   s_arg;
    if (tid == 0) {
        s_lse = shm[0] + __logf(shs[0]);
        s_arg = shidx[0];
    }
    __syncthreads();

    // diagonal S_ii = dot(PN16[row], YN16[row])
    float d = 0.f;
    const __half* pr = g_PN16 + (size_t)row * OUTD;
    const __half* yr = g_YN16 + (size_t)row * OUTD;
#pragma unroll
    for (int i = 0; i < 6; i++) {
        int j = tid + i * 128;
        d += __half2float(pr[j]) * __half2float(yr[j]);
    }
    shm[tid] = d;
    __syncthreads();
    for (int o = 64; o > 0; o >>= 1) {
        if (tid < o) shm[tid] += shm[tid + o];
        __syncthreads();
    }
    if (tid == 0) {
        double contrib = (double)s_lse - (double)shm[0];
        atomicAdd(&g_loss, contrib);
        if (s_arg == row) atomicAdd(&g_correct, 1);
    }
}

__global__ void finalize_kernel(float* __restrict__ out, int out_size)
{
    const int NP = BSZ * OUTD;
    if (out_size >= NP + 2) {
        out[NP]     = (float)g_loss;
        out[NP + 1] = (float)g_correct / (float)BSZ;
    }
}

// ===========================================================================
extern "C" void kernel_launch(void* const* d_in, const int* in_sizes, int n_in,
                              void* d_out, int out_size)
{
    const float* inp  = (const float*)d_in[0];
    const float* y    = (const float*)d_in[1];
    const float* ln1g = (const float*)d_in[2];
    const float* ln1b = (const float*)d_in[3];
    const float* W1   = (const float*)d_in[4];
    const float* b1   = (const float*)d_in[5];
    const float* Wa   = (const float*)d_in[6];
    const float* ba   = (const float*)d_in[7];
    const float* Wb   = (const float*)d_in[8];
    const float* bb   = (const float*)d_in[9];
    const float* W2   = (const float*)d_in[10];
    const float* b2   = (const float*)d_in[11];
    const float* ln2g = (const float*)d_in[12];
    const float* ln2b = (const float*)d_in[13];
    float* out = (float*)d_out;

    static int smem_cfg_done = 0;
    if (!smem_cfg_done) {
        cudaFuncSetAttribute((const void*)tc_gemm<1, false>,
                             cudaFuncAttributeMaxDynamicSharedMemorySize, GEMM_SMEM_BYTES);
        cudaFuncSetAttribute((const void*)tc_gemm<2, false>,
                             cudaFuncAttributeMaxDynamicSharedMemorySize, GEMM_SMEM_BYTES);
        cudaFuncSetAttribute((const void*)tc_gemm<1, true>,
                             cudaFuncAttributeMaxDynamicSharedMemorySize, GEMM_SMEM_BYTES);
        smem_cfg_done = 1;
    }

    float *H, *P;
    cudaGetSymbolAddress((void**)&H, g_H);
    cudaGetSymbolAddress((void**)&P, g_P);
    __half *A1h, *Hh, *Hl, *Th, *PN16, *YN16;
    __half *W1h, *Wah, *Wbh, *W2h;
    cudaGetSymbolAddress((void**)&A1h, g_A1h);
    cudaGetSymbolAddress((void**)&Hh,  g_Hh);
    cudaGetSymbolAddress((void**)&Hl,  g_Hl);
    cudaGetSymbolAddress((void**)&Th,  g_Th);
    cudaGetSymbolAddress((void**)&PN16, g_PN16);
    cudaGetSymbolAddress((void**)&YN16, g_YN16);
    cudaGetSymbolAddress((void**)&W1h, g_W1h);
    cudaGetSymbolAddress((void**)&Wah, g_Wah);
    cudaGetSymbolAddress((void**)&Wbh, g_Wbh);
    cudaGetSymbolAddress((void**)&W2h, g_W2h);

    const int MAXCTA = 304;   // 2 CTAs/SM x 152 SMs
    auto grid_for = [&](int M, int N) {
        int nt = (M >> 7) * (N >> 7);
        return nt < MAXCTA ? nt : MAXCTA;
    };

    tsplit_all_kernel<<<dim3(INPD / 32, HIDD / 32, 4), dim3(32, 8)>>>(W1, Wa, Wb, W2);
    ln1_split_kernel<<<BSZ, 256>>>(inp, ln1g, ln1b);

    // H = LN1(inp) @ W1 + b1 — pure fp16 (1 MMA, 3-stage); f32 H + Hh
    tc_gemm<1, false><<<grid_for(BSZ, HIDD), 256, GEMM_SMEM_BYTES>>>(
        A1h, nullptr, W1h, b1, nullptr, H, Hh, nullptr, BSZ, HIDD, INPD, 0);

    // residual blocks — pure fp16 (1 MMA, 3-stage)
    tc_gemm<1, false><<<grid_for(BSZ, HIDD), 256, GEMM_SMEM_BYTES>>>(
        Hh, nullptr, Wah, ba, nullptr, nullptr, Th, nullptr, BSZ, HIDD, HIDD, 1);
    tc_gemm<1, false><<<grid_for(BSZ, HIDD), 256, GEMM_SMEM_BYTES>>>(
        Th, nullptr, Wbh, bb, H, H, Hh, nullptr, BSZ, HIDD, HIDD, 1);
    tc_gemm<1, false><<<grid_for(BSZ, HIDD), 256, GEMM_SMEM_BYTES>>>(
        Hh, nullptr, Wah, ba, nullptr, nullptr, Th, nullptr, BSZ, HIDD, HIDD, 1);
    tc_gemm<1, false><<<grid_for(BSZ, HIDD), 256, GEMM_SMEM_BYTES>>>(
        Th, nullptr, Wbh, bb, H, H, Hh, Hl, BSZ, HIDD, HIDD, 1);

    // P = H @ W2 + b2 — fp16 A-pair x W2-single (2 MMAs, 2-stage)
    tc_gemm<2, false><<<grid_for(BSZ, OUTD), 256, GEMM_SMEM_BYTES>>>(
        Hh, Hl, W2h, b2, nullptr, P, nullptr, nullptr, BSZ, OUTD, HIDD, 0);

    ln2_norm_kernel<<<BSZ, 256>>>(P, ln2g, ln2b, out);
    ynorm_kernel<<<BSZ, 256>>>(y);

    // S = PN @ YN^T — fp16 single (3-stage), fused online-softmax epilogue
    tc_gemm<1, true><<<grid_for(BSZ, BSZ), 256, GEMM_SMEM_BYTES>>>(
        PN16, nullptr, YN16, nullptr, nullptr, nullptr, nullptr, nullptr,
        BSZ, BSZ, OUTD, 0);

    merge_S_kernel<<<BSZ, 128>>>();
    finalize_kernel<<<1, 1>>>(out, out_size);
}